// round 3
// baseline (speedup 1.0000x reference)
#include <cuda_runtime.h>

typedef unsigned long long ull;

#define NN 100000
#define NE 800000
#define DD 256

// ---------------- device scratch (no allocations allowed) ----------------
__device__ __align__(16) float g_bufA[(size_t)NN * DD];   // Hs (scaled h)
__device__ __align__(16) float g_bufB[(size_t)NN * DD];   // layer output
__device__ int   g_indeg[NN];
__device__ int   g_off[NN + 1];
__device__ int   g_cursor[NN];
__device__ int   g_csrc[NE];
__device__ float g_dis[NN];

// ---------------- graph preprocessing ----------------
__global__ void k_zero() {
    int i = blockIdx.x * 256 + threadIdx.x;
    if (i < NN) g_indeg[i] = 0;
}

__global__ void k_deg(const int* __restrict__ dst) {
    int e = blockIdx.x * 256 + threadIdx.x;
    if (e < NE) atomicAdd(&g_indeg[dst[e]], 1);
}

// single-CTA hierarchical exclusive scan of indeg -> off/cursor, plus dis = rsqrt(deg)
__global__ void k_scan() {
    const int PER = (NN + 1023) / 1024;   // 98
    int tid = threadIdx.x;
    int start = tid * PER;
    int end = start + PER; if (end > NN) end = NN;
    int s = 0;
    for (int i = start; i < end; i++) s += g_indeg[i];

    int lane = tid & 31, w = tid >> 5;
    int v = s;
    #pragma unroll
    for (int d = 1; d < 32; d <<= 1) {
        int t = __shfl_up_sync(0xffffffffu, v, d);
        if (lane >= d) v += t;
    }
    __shared__ int wsum[32];
    if (lane == 31) wsum[w] = v;
    __syncthreads();
    if (w == 0) {
        int u = wsum[lane];
        #pragma unroll
        for (int d = 1; d < 32; d <<= 1) {
            int t = __shfl_up_sync(0xffffffffu, u, d);
            if (lane >= d) u += t;
        }
        wsum[lane] = u;
    }
    __syncthreads();
    int excl = v - s + (w > 0 ? wsum[w - 1] : 0);

    int run = excl;
    for (int i = start; i < end; i++) {
        g_off[i] = run;
        g_cursor[i] = run;
        g_dis[i] = rsqrtf((float)(g_indeg[i] + 1));  // +1 self loop
        run += g_indeg[i];
    }
    if (tid == 1023) g_off[NN] = run;   // = NE (tail threads carry total)
}

__global__ void k_fill(const int* __restrict__ src, const int* __restrict__ dst) {
    int e = blockIdx.x * 256 + threadIdx.x;
    if (e < NE) {
        int p = atomicAdd(&g_cursor[dst[e]], 1);
        g_csrc[p] = src[e];
    }
}

// ---------------- packed f32x2 FMA helpers ----------------
__device__ __forceinline__ void ffma2(ull& c, ull a, ull b) {
    asm("fma.rn.f32x2 %0, %1, %2, %0;" : "+l"(c) : "l"(a), "l"(b));
}
__device__ __forceinline__ ull dupf(float x) {
    union { float2 f; ull u; } v;
    v.f = make_float2(x, x);
    return v.u;
}

// ---------------- SGEMM: C[M,N] = A[M,256] @ W[256,N], BM=128 BN=64 BK=16 ----------------
// MODE 0: A = Aext (x),     C = g_bufA, epilogue row-scale by g_dis
// MODE 1: A = g_bufB,       C = g_bufA, epilogue row-scale by g_dis
// MODE 2: A = g_bufB,       C = Cext,   epilogue + bias (output projection)
template <int MODE>
__global__ __launch_bounds__(256)
void sgemm_k(const float* __restrict__ Aext, const float* __restrict__ W,
             const float* __restrict__ bias, float* __restrict__ Cext, int N)
{
    const float* A = (MODE == 0) ? Aext : (const float*)g_bufB;
    float* C = (MODE == 2) ? Cext : (float*)g_bufA;

    __shared__ float As[16][132];   // [k][m], padded stride (16B aligned rows)
    __shared__ float Bs[16][64];    // [k][n]

    int tid = threadIdx.x;
    int bm0 = blockIdx.x * 128;
    int bn0 = blockIdx.y * 64;
    int ty = tid >> 4, tx = tid & 15;
    int m0 = ty * 8, n0 = tx * 4;

    ull cc[4][4];
    #pragma unroll
    for (int p = 0; p < 4; p++)
        #pragma unroll
        for (int j = 0; j < 4; j++) cc[p][j] = 0ull;

    #pragma unroll 1
    for (int kb = 0; kb < 256; kb += 16) {
        // load A tile 128x16 (transposed into As[k][m]); 2 float4 per thread
        #pragma unroll
        for (int h = 0; h < 2; h++) {
            int id = tid + h * 256;
            int row = id >> 2, kv = id & 3;
            int r = bm0 + row;
            float4 v = make_float4(0.f, 0.f, 0.f, 0.f);
            if (r < NN) v = *(const float4*)(A + (size_t)r * DD + kb + kv * 4);
            As[kv * 4 + 0][row] = v.x;
            As[kv * 4 + 1][row] = v.y;
            As[kv * 4 + 2][row] = v.z;
            As[kv * 4 + 3][row] = v.w;
        }
        // load B tile 16x64; 1 float4 per thread
        {
            int row = tid >> 4, cv = tid & 15;
            float4 v = *(const float4*)(W + (size_t)(kb + row) * N + bn0 + cv * 4);
            *(float4*)&Bs[row][cv * 4] = v;
        }
        __syncthreads();

        #pragma unroll
        for (int k = 0; k < 16; k++) {
            ulonglong2 aA = *(const ulonglong2*)&As[k][m0];       // rows m0..m0+3 packed as 2 pairs
            ulonglong2 aB = *(const ulonglong2*)&As[k][m0 + 4];   // rows m0+4..m0+7
            float4 bq = *(const float4*)&Bs[k][n0];
            ull b0 = dupf(bq.x), b1 = dupf(bq.y), b2 = dupf(bq.z), b3 = dupf(bq.w);
            ffma2(cc[0][0], aA.x, b0); ffma2(cc[0][1], aA.x, b1);
            ffma2(cc[0][2], aA.x, b2); ffma2(cc[0][3], aA.x, b3);
            ffma2(cc[1][0], aA.y, b0); ffma2(cc[1][1], aA.y, b1);
            ffma2(cc[1][2], aA.y, b2); ffma2(cc[1][3], aA.y, b3);
            ffma2(cc[2][0], aB.x, b0); ffma2(cc[2][1], aB.x, b1);
            ffma2(cc[2][2], aB.x, b2); ffma2(cc[2][3], aB.x, b3);
            ffma2(cc[3][0], aB.y, b0); ffma2(cc[3][1], aB.y, b1);
            ffma2(cc[3][2], aB.y, b2); ffma2(cc[3][3], aB.y, b3);
        }
        __syncthreads();
    }

    float bv0 = 0.f, bv1 = 0.f, bv2 = 0.f, bv3 = 0.f;
    if (MODE == 2) {
        float4 bb = *(const float4*)(bias + bn0 + n0);
        bv0 = bb.x; bv1 = bb.y; bv2 = bb.z; bv3 = bb.w;
    }

    #pragma unroll
    for (int p = 0; p < 4; p++) {
        union { ull u; float2 f; } c0, c1, c2, c3;
        c0.u = cc[p][0]; c1.u = cc[p][1]; c2.u = cc[p][2]; c3.u = cc[p][3];
        int r0 = bm0 + m0 + 2 * p;
        if (r0 < NN) {
            float4 o = make_float4(c0.f.x, c1.f.x, c2.f.x, c3.f.x);
            if (MODE == 2) { o.x += bv0; o.y += bv1; o.z += bv2; o.w += bv3; }
            else { float sc = g_dis[r0]; o.x *= sc; o.y *= sc; o.z *= sc; o.w *= sc; }
            *(float4*)(C + (size_t)r0 * N + bn0 + n0) = o;
        }
        int r1 = r0 + 1;
        if (r1 < NN) {
            float4 o = make_float4(c0.f.y, c1.f.y, c2.f.y, c3.f.y);
            if (MODE == 2) { o.x += bv0; o.y += bv1; o.z += bv2; o.w += bv3; }
            else { float sc = g_dis[r1]; o.x *= sc; o.y *= sc; o.z *= sc; o.w *= sc; }
            *(float4*)(C + (size_t)r1 * N + bn0 + n0) = o;
        }
    }
}

// ---------------- aggregation: out[i] = relu(dis[i]*(Hs[i] + sum_{src->i} Hs[src]) + b) ----------------
// one warp per node; reads g_bufA, writes g_bufB
__global__ __launch_bounds__(256)
void k_agg(const float* __restrict__ bias)
{
    int node = blockIdx.x * 8 + (threadIdx.x >> 5);
    int lane = threadIdx.x & 31;
    const float4* __restrict__ Hs = (const float4*)g_bufA;
    float4* __restrict__ Out = (float4*)g_bufB;

    size_t base = (size_t)node * 64;
    float4 a0 = Hs[base + lane];          // self loop
    float4 a1 = Hs[base + 32 + lane];

    int e = g_off[node], end = g_off[node + 1];
    for (; e + 1 < end; e += 2) {
        int s0 = g_csrc[e], s1 = g_csrc[e + 1];
        size_t p0 = (size_t)s0 * 64, p1 = (size_t)s1 * 64;
        float4 v0 = Hs[p0 + lane];
        float4 v1 = Hs[p0 + 32 + lane];
        float4 w0 = Hs[p1 + lane];
        float4 w1 = Hs[p1 + 32 + lane];
        a0.x += v0.x + w0.x; a0.y += v0.y + w0.y; a0.z += v0.z + w0.z; a0.w += v0.w + w0.w;
        a1.x += v1.x + w1.x; a1.y += v1.y + w1.y; a1.z += v1.z + w1.z; a1.w += v1.w + w1.w;
    }
    if (e < end) {
        int s0 = g_csrc[e];
        size_t p0 = (size_t)s0 * 64;
        float4 v0 = Hs[p0 + lane];
        float4 v1 = Hs[p0 + 32 + lane];
        a0.x += v0.x; a0.y += v0.y; a0.z += v0.z; a0.w += v0.w;
        a1.x += v1.x; a1.y += v1.y; a1.z += v1.z; a1.w += v1.w;
    }

    float dsc = g_dis[node];
    float4 b0 = *(const float4*)(bias + lane * 4);
    float4 b1 = *(const float4*)(bias + 128 + lane * 4);
    float4 o0, o1;
    o0.x = fmaxf(fmaf(dsc, a0.x, b0.x), 0.f);
    o0.y = fmaxf(fmaf(dsc, a0.y, b0.y), 0.f);
    o0.z = fmaxf(fmaf(dsc, a0.z, b0.z), 0.f);
    o0.w = fmaxf(fmaf(dsc, a0.w, b0.w), 0.f);
    o1.x = fmaxf(fmaf(dsc, a1.x, b1.x), 0.f);
    o1.y = fmaxf(fmaf(dsc, a1.y, b1.y), 0.f);
    o1.z = fmaxf(fmaf(dsc, a1.z, b1.z), 0.f);
    o1.w = fmaxf(fmaf(dsc, a1.w, b1.w), 0.f);
    Out[base + lane] = o0;
    Out[base + 32 + lane] = o1;
}

// ---------------- log_softmax over 64 cols, warp per row, in-place on d_out ----------------
__global__ __launch_bounds__(256)
void k_lsm(float* __restrict__ out)
{
    int row = blockIdx.x * 8 + (threadIdx.x >> 5);
    int lane = threadIdx.x & 31;
    size_t b = (size_t)row * 64;
    float v0 = out[b + lane];
    float v1 = out[b + 32 + lane];
    float m = fmaxf(v0, v1);
    #pragma unroll
    for (int d = 16; d; d >>= 1) m = fmaxf(m, __shfl_xor_sync(0xffffffffu, m, d));
    float s = expf(v0 - m) + expf(v1 - m);
    #pragma unroll
    for (int d = 16; d; d >>= 1) s += __shfl_xor_sync(0xffffffffu, s, d);
    float l = m + logf(s);
    out[b + lane] = v0 - l;
    out[b + 32 + lane] = v1 - l;
}

// ---------------- launch ----------------
extern "C" void kernel_launch(void* const* d_in, const int* in_sizes, int n_in,
                              void* d_out, int out_size)
{
    const float* x  = (const float*)d_in[0];
    const int*   ei = (const int*)d_in[1];
    const float* W1 = (const float*)d_in[2];
    const float* b1 = (const float*)d_in[3];
    const float* W2 = (const float*)d_in[4];
    const float* b2 = (const float*)d_in[5];
    const float* Wo = (const float*)d_in[6];
    const float* bo = (const float*)d_in[7];
    float* out = (float*)d_out;

    const int* src = ei;
    const int* dst = ei + NE;

    // graph prep: degrees -> CSR -> dis
    k_zero<<<(NN + 255) / 256, 256>>>();
    k_deg<<<NE / 256, 256>>>(dst);
    k_scan<<<1, 1024>>>();
    k_fill<<<NE / 256, 256>>>(src, dst);

    dim3 g1((NN + 127) / 128, DD / 64);
    dim3 g3((NN + 127) / 128, 1);

    // layer 1
    sgemm_k<0><<<g1, 256>>>(x, W1, nullptr, nullptr, DD);       // bufA = dis * (x @ W1)
    k_agg<<<NN / 8, 256>>>(b1);                                 // bufB = relu(...)
    // layer 2
    sgemm_k<1><<<g1, 256>>>(nullptr, W2, nullptr, nullptr, DD); // bufA = dis * (bufB @ W2)
    k_agg<<<NN / 8, 256>>>(b2);                                 // bufB = relu(...)
    // output projection + log_softmax
    sgemm_k<2><<<g3, 256>>>(nullptr, Wo, bo, out, 64);          // out = bufB @ Wo + bo
    k_lsm<<<NN / 8, 256>>>(out);
}

// round 5
// speedup vs baseline: 1.2585x; 1.2585x over previous
#include <cuda_runtime.h>
#include <cuda_bf16.h>
#include <cstdint>

#define NN 100000
#define NE 800000
#define DD 256

// ---------------- device scratch (no allocations allowed) ----------------
__device__ __align__(16) float g_bufA[(size_t)NN * DD];   // Hs (dis-scaled h)
__device__ __align__(16) float g_bufB[(size_t)NN * DD];   // layer output
__device__ int   g_indeg[NN];
__device__ int   g_off[NN + 1];
__device__ int   g_cursor[NN];
__device__ int   g_csrc[NE];
__device__ float g_dis[NN];
// W split hi/lo, pre-transposed to [N][K] bf16 (B operand, K-contiguous)
__device__ __align__(16) __nv_bfloat16 g_W1h[256 * 256], g_W1l[256 * 256];
__device__ __align__(16) __nv_bfloat16 g_W2h[256 * 256], g_W2l[256 * 256];
__device__ __align__(16) __nv_bfloat16 g_Woh[64 * 256],  g_Wol[64 * 256];

// ---------------- PTX helpers (all valid on compute_103: no tcgen05) -----
__device__ __forceinline__ uint32_t smem_u32(const void* p) {
    uint32_t a;
    asm("{ .reg .u64 t; cvta.to.shared.u64 t, %1; cvt.u32.u64 %0, t; }" : "=r"(a) : "l"(p));
    return a;
}
__device__ __forceinline__ void ldsm4(uint32_t r[4], uint32_t addr) {
    asm volatile("ldmatrix.sync.aligned.m8n8.x4.shared.b16 {%0,%1,%2,%3}, [%4];"
                 : "=r"(r[0]), "=r"(r[1]), "=r"(r[2]), "=r"(r[3]) : "r"(addr));
}
__device__ __forceinline__ void mma16816(float c[4], const uint32_t a[4], const uint32_t b[2]) {
    asm volatile(
        "mma.sync.aligned.m16n8k16.row.col.f32.bf16.bf16.f32 "
        "{%0,%1,%2,%3}, {%4,%5,%6,%7}, {%8,%9}, {%0,%1,%2,%3};"
        : "+f"(c[0]), "+f"(c[1]), "+f"(c[2]), "+f"(c[3])
        : "r"(a[0]), "r"(a[1]), "r"(a[2]), "r"(a[3]), "r"(b[0]), "r"(b[1]));
}
__device__ __forceinline__ void sts128(uint32_t addr, uint4 v) {
    asm volatile("st.shared.v4.b32 [%0], {%1,%2,%3,%4};"
                 :: "r"(addr), "r"(v.x), "r"(v.y), "r"(v.z), "r"(v.w) : "memory");
}
__device__ __forceinline__ void sts64(uint32_t addr, uint32_t x, uint32_t y) {
    asm volatile("st.shared.v2.b32 [%0], {%1,%2};" :: "r"(addr), "r"(x), "r"(y) : "memory");
}
// split two fp32 -> packed bf16 hi pair + lo pair
__device__ __forceinline__ void split2(float f0, float f1, uint32_t& h, uint32_t& l) {
    __nv_bfloat16 h0 = __float2bfloat16(f0), h1 = __float2bfloat16(f1);
    __nv_bfloat16 l0 = __float2bfloat16(f0 - __bfloat162float(h0));
    __nv_bfloat16 l1 = __float2bfloat16(f1 - __bfloat162float(h1));
    h = (uint32_t)*(uint16_t*)&h0 | ((uint32_t)*(uint16_t*)&h1 << 16);
    l = (uint32_t)*(uint16_t*)&l0 | ((uint32_t)*(uint16_t*)&l1 << 16);
}

// ---------------- graph preprocessing ----------------
__global__ void k_zero() {
    int i = blockIdx.x * 256 + threadIdx.x;
    if (i < NN) g_indeg[i] = 0;
}
__global__ void k_deg(const int* __restrict__ dst) {
    int e = blockIdx.x * 256 + threadIdx.x;
    if (e < NE) atomicAdd(&g_indeg[dst[e]], 1);
}
__global__ void k_scan() {
    const int PER = (NN + 1023) / 1024;
    int tid = threadIdx.x;
    int start = tid * PER;
    int end = start + PER; if (end > NN) end = NN;
    int s = 0;
    for (int i = start; i < end; i++) s += g_indeg[i];
    int lane = tid & 31, w = tid >> 5;
    int v = s;
    #pragma unroll
    for (int d = 1; d < 32; d <<= 1) {
        int t = __shfl_up_sync(0xffffffffu, v, d);
        if (lane >= d) v += t;
    }
    __shared__ int wsum[32];
    if (lane == 31) wsum[w] = v;
    __syncthreads();
    if (w == 0) {
        int u = wsum[lane];
        #pragma unroll
        for (int d = 1; d < 32; d <<= 1) {
            int t = __shfl_up_sync(0xffffffffu, u, d);
            if (lane >= d) u += t;
        }
        wsum[lane] = u;
    }
    __syncthreads();
    int excl = v - s + (w > 0 ? wsum[w - 1] : 0);
    int run = excl;
    for (int i = start; i < end; i++) {
        g_off[i] = run;
        g_cursor[i] = run;
        g_dis[i] = rsqrtf((float)(g_indeg[i] + 1));
        run += g_indeg[i];
    }
    if (tid == 1023) g_off[NN] = run;
}
__global__ void k_fill(const int* __restrict__ src, const int* __restrict__ dst) {
    int e = blockIdx.x * 256 + threadIdx.x;
    if (e < NE) {
        int p = atomicAdd(&g_cursor[dst[e]], 1);
        g_csrc[p] = src[e];
    }
}

// ---------------- weight split + transpose (once per launch) ----------------
__global__ void k_convW(const float* __restrict__ W1, const float* __restrict__ W2,
                        const float* __restrict__ Wo) {
    int idx = blockIdx.x * 256 + threadIdx.x;
    if (idx < 65536) {
        int n = idx >> 8, k = idx & 255;
        float a = W1[(size_t)k * 256 + n];
        __nv_bfloat16 h = __float2bfloat16(a);
        g_W1h[idx] = h;
        g_W1l[idx] = __float2bfloat16(a - __bfloat162float(h));
        a = W2[(size_t)k * 256 + n];
        h = __float2bfloat16(a);
        g_W2h[idx] = h;
        g_W2l[idx] = __float2bfloat16(a - __bfloat162float(h));
        if (idx < 16384) {
            int n2 = idx >> 8, k2 = idx & 255;
            a = Wo[(size_t)k2 * 64 + n2];
            h = __float2bfloat16(a);
            g_Woh[idx] = h;
            g_Wol[idx] = __float2bfloat16(a - __bfloat162float(h));
        }
    }
}

// ---------------- HMMA GEMM: C[M,N] = A[M,256] @ W, 3-pass bf16 split --------
// BM=128, BK=32, 256 thr (8 warps, 4m x 2n), warp tile 32 x (BN/2).
// MODE 0: A=x ext,  C=g_bufA (row-scale by dis)
// MODE 1: A=g_bufB, C=g_bufA (row-scale by dis)
// MODE 2: A=g_bufB, C=Cext   (+ bias), BN=64
template <int MODE, int BN>
__global__ __launch_bounds__(256)
void gemm_mma(const float* __restrict__ Aext, const float* __restrict__ bias,
              float* __restrict__ Cext)
{
    const float* A = (MODE == 0) ? Aext : (const float*)g_bufB;
    float* C = (MODE == 2) ? Cext : (float*)g_bufA;
    const __nv_bfloat16* WH = (MODE == 0) ? g_W1h : (MODE == 1) ? g_W2h : g_Woh;
    const __nv_bfloat16* WL = (MODE == 0) ? g_W1l : (MODE == 1) ? g_W2l : g_Wol;

    constexpr int WN = BN / 2;            // 64 or 32
    constexpr int NT = WN / 8;            // 8 or 4
    constexpr int LDSE = 40;              // padded row stride, elems (80B)
    constexpr int A_BYTES = 128 * LDSE * 2;       // 10240
    constexpr int B_BYTES = BN * LDSE * 2;
    constexpr int STAGE = 2 * A_BYTES + 2 * B_BYTES;
    constexpr int BH = (BN == 128) ? 2 : 1;       // B load iterations
    constexpr int CS = (MODE == 2) ? 64 : 256;    // C row stride

    extern __shared__ char smraw[];
    uint32_t sb = smem_u32(smraw);

    int tid = threadIdx.x, lane = tid & 31, wid = tid >> 5;
    int mw = wid & 3, nw = wid >> 2;
    int bm0 = blockIdx.x * 128;
    int bn0 = blockIdx.y * BN;

    // staging slices
    int arow = tid >> 1;
    int akoff = (tid & 1) * 16;
    int ar = bm0 + arow;
    const float* aptr = A + (size_t)ar * DD + akoff;
    bool avalid = (ar < NN);

    float areg[16];
    uint4 bregH[BH], bregL[BH];

    float acc[2][NT][4];
    #pragma unroll
    for (int mt = 0; mt < 2; mt++)
        #pragma unroll
        for (int nt = 0; nt < NT; nt++)
            #pragma unroll
            for (int q = 0; q < 4; q++) acc[mt][nt][q] = 0.f;

    // ---- prologue: chunk 0 -> regs -> smem ----
    {
        #pragma unroll
        for (int g = 0; g < 4; g++) {
            float4 v = avalid ? *(const float4*)(aptr + g * 4)
                              : make_float4(0.f, 0.f, 0.f, 0.f);
            areg[g * 4 + 0] = v.x; areg[g * 4 + 1] = v.y;
            areg[g * 4 + 2] = v.z; areg[g * 4 + 3] = v.w;
        }
        #pragma unroll
        for (int h = 0; h < BH; h++) {
            int id = tid + h * 256;
            int row = id >> 2, k0 = (id & 3) * 8;
            size_t gp = (size_t)(bn0 + row) * DD + k0;
            bregH[h] = *(const uint4*)(WH + gp);
            bregL[h] = *(const uint4*)(WL + gp);
        }
    }

    for (int kb = 0; kb < 8; kb++) {
        int s = kb & 1;
        // store staged regs into stage s (chunk kb)
        {
            uint32_t base = sb + (uint32_t)s * STAGE;
            uint32_t aoff = (uint32_t)arow * 80u + (uint32_t)akoff * 2u;
            #pragma unroll
            for (int g = 0; g < 4; g++) {
                uint32_t h0, l0, h1, l1;
                split2(areg[g * 4 + 0], areg[g * 4 + 1], h0, l0);
                split2(areg[g * 4 + 2], areg[g * 4 + 3], h1, l1);
                sts64(base + aoff + g * 8, h0, h1);
                sts64(base + A_BYTES + aoff + g * 8, l0, l1);
            }
            #pragma unroll
            for (int h = 0; h < BH; h++) {
                int id = tid + h * 256;
                int row = id >> 2, k0 = (id & 3) * 8;
                uint32_t boff = (uint32_t)row * 80u + (uint32_t)k0 * 2u;
                sts128(base + 2 * A_BYTES + boff, bregH[h]);
                sts128(base + 2 * A_BYTES + B_BYTES + boff, bregL[h]);
            }
        }
        __syncthreads();

        // prefetch chunk kb+1 into regs (overlaps with compute below)
        if (kb < 7) {
            int kn = (kb + 1) * 32;
            #pragma unroll
            for (int g = 0; g < 4; g++) {
                float4 v = avalid ? *(const float4*)(aptr + kn + g * 4)
                                  : make_float4(0.f, 0.f, 0.f, 0.f);
                areg[g * 4 + 0] = v.x; areg[g * 4 + 1] = v.y;
                areg[g * 4 + 2] = v.z; areg[g * 4 + 3] = v.w;
            }
            #pragma unroll
            for (int h = 0; h < BH; h++) {
                int id = tid + h * 256;
                int row = id >> 2, k0 = (id & 3) * 8;
                size_t gp = (size_t)(bn0 + row) * DD + kn + k0;
                bregH[h] = *(const uint4*)(WH + gp);
                bregL[h] = *(const uint4*)(WL + gp);
            }
        }

        // compute on stage s
        {
            uint32_t base = sb + (uint32_t)s * STAGE;
            uint32_t aHiB = base, aLoB = base + A_BYTES;
            uint32_t bHiB = base + 2 * A_BYTES, bLoB = bHiB + B_BYTES;
            #pragma unroll
            for (int ks = 0; ks < 2; ks++) {
                int col = ks * 16 + (lane >> 4) * 8;
                uint32_t ah[2][4], al[2][4];
                uint32_t aoff = (uint32_t)((mw * 32 + (lane & 15)) * LDSE + col) * 2u;
                ldsm4(ah[0], aHiB + aoff);
                ldsm4(ah[1], aHiB + aoff + 16 * LDSE * 2);
                ldsm4(al[0], aLoB + aoff);
                ldsm4(al[1], aLoB + aoff + 16 * LDSE * 2);

                uint32_t bh[NT][2], bl[NT][2];
                #pragma unroll
                for (int j = 0; j < NT / 2; j++) {
                    uint32_t boff = (uint32_t)((nw * WN + j * 16 + (lane & 15)) * LDSE + col) * 2u;
                    uint32_t r[4];
                    ldsm4(r, bHiB + boff);
                    bh[2 * j][0] = r[0]; bh[2 * j][1] = r[2];
                    bh[2 * j + 1][0] = r[1]; bh[2 * j + 1][1] = r[3];
                    ldsm4(r, bLoB + boff);
                    bl[2 * j][0] = r[0]; bl[2 * j][1] = r[2];
                    bl[2 * j + 1][0] = r[1]; bl[2 * j + 1][1] = r[3];
                }
                #pragma unroll
                for (int mt = 0; mt < 2; mt++)
                    #pragma unroll
                    for (int nt = 0; nt < NT; nt++) {
                        mma16816(acc[mt][nt], ah[mt], bh[nt]);
                        mma16816(acc[mt][nt], ah[mt], bl[nt]);
                        mma16816(acc[mt][nt], al[mt], bh[nt]);
                    }
            }
        }
        __syncthreads();
    }

    // ---- epilogue ----
    int rbase = bm0 + mw * 32 + (lane >> 2);
    int cbase = bn0 + nw * WN + (lane & 3) * 2;
    #pragma unroll
    for (int mt = 0; mt < 2; mt++) {
        int r0 = rbase + mt * 16, r1 = r0 + 8;
        float s0 = 1.f, s1 = 1.f;
        if (MODE != 2) {
            s0 = (r0 < NN) ? g_dis[r0] : 0.f;
            s1 = (r1 < NN) ? g_dis[r1] : 0.f;
        }
        #pragma unroll
        for (int nt = 0; nt < NT; nt++) {
            int cc = cbase + nt * 8;
            float v0 = acc[mt][nt][0], v1 = acc[mt][nt][1];
            float v2 = acc[mt][nt][2], v3 = acc[mt][nt][3];
            if (MODE == 2) {
                float b0 = bias[cc], b1 = bias[cc + 1];
                if (r0 < NN) *(float2*)(C + (size_t)r0 * CS + cc) = make_float2(v0 + b0, v1 + b1);
                if (r1 < NN) *(float2*)(C + (size_t)r1 * CS + cc) = make_float2(v2 + b0, v3 + b1);
            } else {
                if (r0 < NN) *(float2*)(C + (size_t)r0 * CS + cc) = make_float2(v0 * s0, v1 * s0);
                if (r1 < NN) *(float2*)(C + (size_t)r1 * CS + cc) = make_float2(v2 * s1, v3 * s1);
            }
        }
    }
}

// ---------------- aggregation: out[i] = relu(dis[i]*(Hs[i] + sum_{src->i} Hs[src]) + b) ----------------
__global__ __launch_bounds__(256)
void k_agg(const float* __restrict__ bias)
{
    int node = blockIdx.x * 8 + (threadIdx.x >> 5);
    int lane = threadIdx.x & 31;
    const float4* __restrict__ Hs = (const float4*)g_bufA;
    float4* __restrict__ Out = (float4*)g_bufB;

    size_t base = (size_t)node * 64;
    float4 a0 = Hs[base + lane];
    float4 a1 = Hs[base + 32 + lane];

    int e = g_off[node], end = g_off[node + 1];
    for (; e + 1 < end; e += 2) {
        int s0 = g_csrc[e], s1 = g_csrc[e + 1];
        size_t p0 = (size_t)s0 * 64, p1 = (size_t)s1 * 64;
        float4 v0 = Hs[p0 + lane];
        float4 v1 = Hs[p0 + 32 + lane];
        float4 w0 = Hs[p1 + lane];
        float4 w1 = Hs[p1 + 32 + lane];
        a0.x += v0.x + w0.x; a0.y += v0.y + w0.y; a0.z += v0.z + w0.z; a0.w += v0.w + w0.w;
        a1.x += v1.x + w1.x; a1.y += v1.y + w1.y; a1.z += v1.z + w1.z; a1.w += v1.w + w1.w;
    }
    if (e < end) {
        int s0 = g_csrc[e];
        size_t p0 = (size_t)s0 * 64;
        float4 v0 = Hs[p0 + lane];
        float4 v1 = Hs[p0 + 32 + lane];
        a0.x += v0.x; a0.y += v0.y; a0.z += v0.z; a0.w += v0.w;
        a1.x += v1.x; a1.y += v1.y; a1.z += v1.z; a1.w += v1.w;
    }

    float dsc = g_dis[node];
    float4 b0 = *(const float4*)(bias + lane * 4);
    float4 b1 = *(const float4*)(bias + 128 + lane * 4);
    float4 o0, o1;
    o0.x = fmaxf(fmaf(dsc, a0.x, b0.x), 0.f);
    o0.y = fmaxf(fmaf(dsc, a0.y, b0.y), 0.f);
    o0.z = fmaxf(fmaf(dsc, a0.z, b0.z), 0.f);
    o0.w = fmaxf(fmaf(dsc, a0.w, b0.w), 0.f);
    o1.x = fmaxf(fmaf(dsc, a1.x, b1.x), 0.f);
    o1.y = fmaxf(fmaf(dsc, a1.y, b1.y), 0.f);
    o1.z = fmaxf(fmaf(dsc, a1.z, b1.z), 0.f);
    o1.w = fmaxf(fmaf(dsc, a1.w, b1.w), 0.f);
    Out[base + lane] = o0;
    Out[base + 32 + lane] = o1;
}

// ---------------- log_softmax over 64 cols, warp per row, in-place ----------------
__global__ __launch_bounds__(256)
void k_lsm(float* __restrict__ out)
{
    int row = blockIdx.x * 8 + (threadIdx.x >> 5);
    int lane = threadIdx.x & 31;
    size_t b = (size_t)row * 64;
    float v0 = out[b + lane];
    float v1 = out[b + 32 + lane];
    float m = fmaxf(v0, v1);
    #pragma unroll
    for (int d = 16; d; d >>= 1) m = fmaxf(m, __shfl_xor_sync(0xffffffffu, m, d));
    float s = expf(v0 - m) + expf(v1 - m);
    #pragma unroll
    for (int d = 16; d; d >>= 1) s += __shfl_xor_sync(0xffffffffu, s, d);
    float l = m + logf(s);
    out[b + lane] = v0 - l;
    out[b + 32 + lane] = v1 - l;
}

// ---------------- launch ----------------
extern "C" void kernel_launch(void* const* d_in, const int* in_sizes, int n_in,
                              void* d_out, int out_size)
{
    const float* x  = (const float*)d_in[0];
    const int*   ei = (const int*)d_in[1];
    const float* W1 = (const float*)d_in[2];
    const float* b1 = (const float*)d_in[3];
    const float* W2 = (const float*)d_in[4];
    const float* b2 = (const float*)d_in[5];
    const float* Wo = (const float*)d_in[6];
    const float* bo = (const float*)d_in[7];
    float* out = (float*)d_out;

    const int* src = ei;
    const int* dst = ei + NE;

    // smem: BN=128 stage = 2*10240 + 2*128*80 = 40960 -> 81920 total
    //       BN=64  stage = 2*10240 + 2*64*80  = 30720 -> 61440 total
    cudaFuncSetAttribute(gemm_mma<0, 128>, cudaFuncAttributeMaxDynamicSharedMemorySize, 81920);
    cudaFuncSetAttribute(gemm_mma<1, 128>, cudaFuncAttributeMaxDynamicSharedMemorySize, 81920);
    cudaFuncSetAttribute(gemm_mma<2, 64>,  cudaFuncAttributeMaxDynamicSharedMemorySize, 61440);

    // graph prep + weight split
    k_zero<<<(NN + 255) / 256, 256>>>();
    k_deg<<<NE / 256, 256>>>(dst);
    k_convW<<<256, 256>>>(W1, W2, Wo);
    k_scan<<<1, 1024>>>();
    k_fill<<<NE / 256, 256>>>(src, dst);

    const int GM = (NN + 127) / 128;   // 782

    // layer 1
    gemm_mma<0, 128><<<dim3(GM, 2), 256, 81920>>>(x, nullptr, nullptr);  // bufA = dis*(x@W1)
    k_agg<<<NN / 8, 256>>>(b1);                                          // bufB = relu(...)
    // layer 2
    gemm_mma<1, 128><<<dim3(GM, 2), 256, 81920>>>(nullptr, nullptr, nullptr);
    k_agg<<<NN / 8, 256>>>(b2);
    // output projection + log_softmax
    gemm_mma<2, 64><<<dim3(GM, 1), 256, 61440>>>(nullptr, bo, out);
    k_lsm<<<NN / 8, 256>>>(out);
}

// round 6
// speedup vs baseline: 1.6671x; 1.3247x over previous
#include <cuda_runtime.h>
#include <cuda_bf16.h>
#include <cstdint>

#define NN 100000
#define NE 800000
#define DD 256

// ---------------- device scratch (no allocations allowed) ----------------
__device__ __align__(16) float g_bufA[(size_t)NN * DD];   // Hs (dis-scaled h)
__device__ __align__(16) float g_bufB[(size_t)NN * DD];   // layer output
__device__ int   g_indeg[NN];
__device__ int   g_off[NN];
__device__ int   g_cursor[NN];
__device__ int   g_csrc[NE];
__device__ float g_dis[NN];
__device__ int   g_total;
// W split hi/lo, pre-transposed to [N][K] bf16 (B operand, K-contiguous)
__device__ __align__(16) __nv_bfloat16 g_W1h[256 * 256], g_W1l[256 * 256];
__device__ __align__(16) __nv_bfloat16 g_W2h[256 * 256], g_W2l[256 * 256];
__device__ __align__(16) __nv_bfloat16 g_Woh[64 * 256],  g_Wol[64 * 256];

// ---------------- PTX helpers (all valid on compute_103: no tcgen05) -----
__device__ __forceinline__ uint32_t smem_u32(const void* p) {
    uint32_t a;
    asm("{ .reg .u64 t; cvta.to.shared.u64 t, %1; cvt.u32.u64 %0, t; }" : "=r"(a) : "l"(p));
    return a;
}
__device__ __forceinline__ void ldsm4(uint32_t r[4], uint32_t addr) {
    asm volatile("ldmatrix.sync.aligned.m8n8.x4.shared.b16 {%0,%1,%2,%3}, [%4];"
                 : "=r"(r[0]), "=r"(r[1]), "=r"(r[2]), "=r"(r[3]) : "r"(addr));
}
__device__ __forceinline__ void mma16816(float c[4], const uint32_t a[4], const uint32_t b[2]) {
    asm volatile(
        "mma.sync.aligned.m16n8k16.row.col.f32.bf16.bf16.f32 "
        "{%0,%1,%2,%3}, {%4,%5,%6,%7}, {%8,%9}, {%0,%1,%2,%3};"
        : "+f"(c[0]), "+f"(c[1]), "+f"(c[2]), "+f"(c[3])
        : "r"(a[0]), "r"(a[1]), "r"(a[2]), "r"(a[3]), "r"(b[0]), "r"(b[1]));
}
__device__ __forceinline__ void sts128(uint32_t addr, uint4 v) {
    asm volatile("st.shared.v4.b32 [%0], {%1,%2,%3,%4};"
                 :: "r"(addr), "r"(v.x), "r"(v.y), "r"(v.z), "r"(v.w) : "memory");
}
__device__ __forceinline__ void sts64(uint32_t addr, uint32_t x, uint32_t y) {
    asm volatile("st.shared.v2.b32 [%0], {%1,%2};" :: "r"(addr), "r"(x), "r"(y) : "memory");
}
// split two fp32 -> packed bf16 hi pair + lo pair
__device__ __forceinline__ void split2(float f0, float f1, uint32_t& h, uint32_t& l) {
    __nv_bfloat16 h0 = __float2bfloat16(f0), h1 = __float2bfloat16(f1);
    __nv_bfloat16 l0 = __float2bfloat16(f0 - __bfloat162float(h0));
    __nv_bfloat16 l1 = __float2bfloat16(f1 - __bfloat162float(h1));
    h = (uint32_t)*(uint16_t*)&h0 | ((uint32_t)*(uint16_t*)&h1 << 16);
    l = (uint32_t)*(uint16_t*)&l0 | ((uint32_t)*(uint16_t*)&l1 << 16);
}

// ---------------- graph preprocessing ----------------
__global__ void k_zero() {
    int i = blockIdx.x * 256 + threadIdx.x;
    if (i < NN) g_indeg[i] = 0;
    if (i == 0) g_total = 0;
}
__global__ void k_deg(const int* __restrict__ dst) {
    int e = blockIdx.x * 256 + threadIdx.x;
    if (e < NE) atomicAdd(&g_indeg[dst[e]], 1);
}
// parallel offset assignment: warp scan + one atomic per warp (order-free CSR)
__global__ void k_off() {
    int i = blockIdx.x * 256 + threadIdx.x;
    int lane = threadIdx.x & 31;
    int d = (i < NN) ? g_indeg[i] : 0;
    int v = d;
    #pragma unroll
    for (int s = 1; s < 32; s <<= 1) {
        int t = __shfl_up_sync(0xffffffffu, v, s);
        if (lane >= s) v += t;
    }
    int wtotal = __shfl_sync(0xffffffffu, v, 31);
    int base = 0;
    if (lane == 0) base = atomicAdd(&g_total, wtotal);
    base = __shfl_sync(0xffffffffu, base, 0);
    if (i < NN) {
        int excl = base + v - d;
        g_off[i] = excl;
        g_cursor[i] = excl;
        g_dis[i] = rsqrtf((float)(d + 1));
    }
}
__global__ void k_fill(const int* __restrict__ src, const int* __restrict__ dst) {
    int e = blockIdx.x * 256 + threadIdx.x;
    if (e < NE) {
        int p = atomicAdd(&g_cursor[dst[e]], 1);
        g_csrc[p] = src[e];
    }
}

// ---------------- weight split + transpose (once per launch) ----------------
__global__ void k_convW(const float* __restrict__ W1, const float* __restrict__ W2,
                        const float* __restrict__ Wo) {
    int idx = blockIdx.x * 256 + threadIdx.x;
    if (idx < 65536) {
        int n = idx >> 8, k = idx & 255;
        float a = W1[(size_t)k * 256 + n];
        __nv_bfloat16 h = __float2bfloat16(a);
        g_W1h[idx] = h;
        g_W1l[idx] = __float2bfloat16(a - __bfloat162float(h));
        a = W2[(size_t)k * 256 + n];
        h = __float2bfloat16(a);
        g_W2h[idx] = h;
        g_W2l[idx] = __float2bfloat16(a - __bfloat162float(h));
        if (idx < 16384) {
            int n2 = idx >> 8, k2 = idx & 255;
            a = Wo[(size_t)k2 * 64 + n2];
            h = __float2bfloat16(a);
            g_Woh[idx] = h;
            g_Wol[idx] = __float2bfloat16(a - __bfloat162float(h));
        }
    }
}

// ---------------- HMMA GEMM: C[M,N] = A[M,256] @ W, 3-pass bf16 split --------
// BM=128, BK=32, 256 thr (8 warps, 4m x 2n), warp tile 32 x (BN/2).
// MODE 0: A=x ext,  C=g_bufA (row-scale by dis)
// MODE 1: A=g_bufB, C=g_bufA (row-scale by dis)
// MODE 2: A=g_bufB, C=Cext   (+ bias), BN=64
template <int MODE, int BN>
__global__ __launch_bounds__(256)
void gemm_mma(const float* __restrict__ Aext, const float* __restrict__ bias,
              float* __restrict__ Cext)
{
    const float* A = (MODE == 0) ? Aext : (const float*)g_bufB;
    float* C = (MODE == 2) ? Cext : (float*)g_bufA;
    const __nv_bfloat16* WH = (MODE == 0) ? g_W1h : (MODE == 1) ? g_W2h : g_Woh;
    const __nv_bfloat16* WL = (MODE == 0) ? g_W1l : (MODE == 1) ? g_W2l : g_Wol;

    constexpr int WN = BN / 2;            // 64 or 32
    constexpr int NT = WN / 8;            // 8 or 4
    constexpr int LDSE = 40;              // padded row stride, elems (80B)
    constexpr int A_BYTES = 128 * LDSE * 2;       // 10240
    constexpr int B_BYTES = BN * LDSE * 2;
    constexpr int STAGE = 2 * A_BYTES + 2 * B_BYTES;
    constexpr int BH = (BN == 128) ? 2 : 1;       // B load iterations
    constexpr int CS = (MODE == 2) ? 64 : 256;    // C row stride

    extern __shared__ char smraw[];
    uint32_t sb = smem_u32(smraw);

    int tid = threadIdx.x, lane = tid & 31, wid = tid >> 5;
    int mw = wid & 3, nw = wid >> 2;
    int bm0 = blockIdx.x * 128;
    int bn0 = blockIdx.y * BN;

    // staging slices
    int arow = tid >> 1;
    int akoff = (tid & 1) * 16;
    int ar = bm0 + arow;
    const float* aptr = A + (size_t)ar * DD + akoff;
    bool avalid = (ar < NN);

    float areg[16];
    uint4 bregH[BH], bregL[BH];

    float acc[2][NT][4];
    #pragma unroll
    for (int mt = 0; mt < 2; mt++)
        #pragma unroll
        for (int nt = 0; nt < NT; nt++)
            #pragma unroll
            for (int q = 0; q < 4; q++) acc[mt][nt][q] = 0.f;

    // ---- prologue: chunk 0 -> regs ----
    {
        #pragma unroll
        for (int g = 0; g < 4; g++) {
            float4 v = avalid ? *(const float4*)(aptr + g * 4)
                              : make_float4(0.f, 0.f, 0.f, 0.f);
            areg[g * 4 + 0] = v.x; areg[g * 4 + 1] = v.y;
            areg[g * 4 + 2] = v.z; areg[g * 4 + 3] = v.w;
        }
        #pragma unroll
        for (int h = 0; h < BH; h++) {
            int id = tid + h * 256;
            int row = id >> 2, k0 = (id & 3) * 8;
            size_t gp = (size_t)(bn0 + row) * DD + k0;
            bregH[h] = *(const uint4*)(WH + gp);
            bregL[h] = *(const uint4*)(WL + gp);
        }
    }

    for (int kb = 0; kb < 8; kb++) {
        int s = kb & 1;
        // store staged regs into stage s (chunk kb)
        {
            uint32_t base = sb + (uint32_t)s * STAGE;
            uint32_t aoff = (uint32_t)arow * 80u + (uint32_t)akoff * 2u;
            #pragma unroll
            for (int g = 0; g < 4; g++) {
                uint32_t h0, l0, h1, l1;
                split2(areg[g * 4 + 0], areg[g * 4 + 1], h0, l0);
                split2(areg[g * 4 + 2], areg[g * 4 + 3], h1, l1);
                sts64(base + aoff + g * 8, h0, h1);
                sts64(base + A_BYTES + aoff + g * 8, l0, l1);
            }
            #pragma unroll
            for (int h = 0; h < BH; h++) {
                int id = tid + h * 256;
                int row = id >> 2, k0 = (id & 3) * 8;
                uint32_t boff = (uint32_t)row * 80u + (uint32_t)k0 * 2u;
                sts128(base + 2 * A_BYTES + boff, bregH[h]);
                sts128(base + 2 * A_BYTES + B_BYTES + boff, bregL[h]);
            }
        }
        __syncthreads();

        // prefetch chunk kb+1 into regs (overlaps with compute below)
        if (kb < 7) {
            int kn = (kb + 1) * 32;
            #pragma unroll
            for (int g = 0; g < 4; g++) {
                float4 v = avalid ? *(const float4*)(aptr + kn + g * 4)
                                  : make_float4(0.f, 0.f, 0.f, 0.f);
                areg[g * 4 + 0] = v.x; areg[g * 4 + 1] = v.y;
                areg[g * 4 + 2] = v.z; areg[g * 4 + 3] = v.w;
            }
            #pragma unroll
            for (int h = 0; h < BH; h++) {
                int id = tid + h * 256;
                int row = id >> 2, k0 = (id & 3) * 8;
                size_t gp = (size_t)(bn0 + row) * DD + kn + k0;
                bregH[h] = *(const uint4*)(WH + gp);
                bregL[h] = *(const uint4*)(WL + gp);
            }
        }

        // compute on stage s
        {
            uint32_t base = sb + (uint32_t)s * STAGE;
            uint32_t aHiB = base, aLoB = base + A_BYTES;
            uint32_t bHiB = base + 2 * A_BYTES, bLoB = bHiB + B_BYTES;
            #pragma unroll
            for (int ks = 0; ks < 2; ks++) {
                int col = ks * 16 + (lane >> 4) * 8;
                uint32_t ah[2][4], al[2][4];
                uint32_t aoff = (uint32_t)((mw * 32 + (lane & 15)) * LDSE + col) * 2u;
                ldsm4(ah[0], aHiB + aoff);
                ldsm4(ah[1], aHiB + aoff + 16 * LDSE * 2);
                ldsm4(al[0], aLoB + aoff);
                ldsm4(al[1], aLoB + aoff + 16 * LDSE * 2);

                uint32_t bh[NT][2], bl[NT][2];
                #pragma unroll
                for (int j = 0; j < NT / 2; j++) {
                    uint32_t boff = (uint32_t)((nw * WN + j * 16 + (lane & 15)) * LDSE + col) * 2u;
                    uint32_t r[4];
                    ldsm4(r, bHiB + boff);
                    bh[2 * j][0] = r[0]; bh[2 * j][1] = r[2];
                    bh[2 * j + 1][0] = r[1]; bh[2 * j + 1][1] = r[3];
                    ldsm4(r, bLoB + boff);
                    bl[2 * j][0] = r[0]; bl[2 * j][1] = r[2];
                    bl[2 * j + 1][0] = r[1]; bl[2 * j + 1][1] = r[3];
                }
                #pragma unroll
                for (int mt = 0; mt < 2; mt++)
                    #pragma unroll
                    for (int nt = 0; nt < NT; nt++) {
                        mma16816(acc[mt][nt], ah[mt], bh[nt]);
                        mma16816(acc[mt][nt], ah[mt], bl[nt]);
                        mma16816(acc[mt][nt], al[mt], bh[nt]);
                    }
            }
        }
        __syncthreads();
    }

    // ---- epilogue ----
    int rbase = bm0 + mw * 32 + (lane >> 2);
    int cbase = bn0 + nw * WN + (lane & 3) * 2;
    #pragma unroll
    for (int mt = 0; mt < 2; mt++) {
        int r0 = rbase + mt * 16, r1 = r0 + 8;
        float s0 = 1.f, s1 = 1.f;
        if (MODE != 2) {
            s0 = (r0 < NN) ? g_dis[r0] : 0.f;
            s1 = (r1 < NN) ? g_dis[r1] : 0.f;
        }
        #pragma unroll
        for (int nt = 0; nt < NT; nt++) {
            int cc = cbase + nt * 8;
            float v0 = acc[mt][nt][0], v1 = acc[mt][nt][1];
            float v2 = acc[mt][nt][2], v3 = acc[mt][nt][3];
            if (MODE == 2) {
                float b0 = bias[cc], b1 = bias[cc + 1];
                if (r0 < NN) *(float2*)(C + (size_t)r0 * CS + cc) = make_float2(v0 + b0, v1 + b1);
                if (r1 < NN) *(float2*)(C + (size_t)r1 * CS + cc) = make_float2(v2 + b0, v3 + b1);
            } else {
                if (r0 < NN) *(float2*)(C + (size_t)r0 * CS + cc) = make_float2(v0 * s0, v1 * s0);
                if (r1 < NN) *(float2*)(C + (size_t)r1 * CS + cc) = make_float2(v2 * s1, v3 * s1);
            }
        }
    }
}

// ---------------- aggregation: out[i] = relu(dis[i]*(Hs[i] + sum_{src->i} Hs[src]) + b) ----------------
__global__ __launch_bounds__(256)
void k_agg(const float* __restrict__ bias)
{
    int node = blockIdx.x * 8 + (threadIdx.x >> 5);
    int lane = threadIdx.x & 31;
    const float4* __restrict__ Hs = (const float4*)g_bufA;
    float4* __restrict__ Out = (float4*)g_bufB;

    size_t base = (size_t)node * 64;
    float4 a0 = Hs[base + lane];
    float4 a1 = Hs[base + 32 + lane];

    int e = g_off[node], end = e + g_indeg[node];
    for (; e + 1 < end; e += 2) {
        int s0 = g_csrc[e], s1 = g_csrc[e + 1];
        size_t p0 = (size_t)s0 * 64, p1 = (size_t)s1 * 64;
        float4 v0 = Hs[p0 + lane];
        float4 v1 = Hs[p0 + 32 + lane];
        float4 w0 = Hs[p1 + lane];
        float4 w1 = Hs[p1 + 32 + lane];
        a0.x += v0.x + w0.x; a0.y += v0.y + w0.y; a0.z += v0.z + w0.z; a0.w += v0.w + w0.w;
        a1.x += v1.x + w1.x; a1.y += v1.y + w1.y; a1.z += v1.z + w1.z; a1.w += v1.w + w1.w;
    }
    if (e < end) {
        int s0 = g_csrc[e];
        size_t p0 = (size_t)s0 * 64;
        float4 v0 = Hs[p0 + lane];
        float4 v1 = Hs[p0 + 32 + lane];
        a0.x += v0.x; a0.y += v0.y; a0.z += v0.z; a0.w += v0.w;
        a1.x += v1.x; a1.y += v1.y; a1.z += v1.z; a1.w += v1.w;
    }

    float dsc = g_dis[node];
    float4 b0 = *(const float4*)(bias + lane * 4);
    float4 b1 = *(const float4*)(bias + 128 + lane * 4);
    float4 o0, o1;
    o0.x = fmaxf(fmaf(dsc, a0.x, b0.x), 0.f);
    o0.y = fmaxf(fmaf(dsc, a0.y, b0.y), 0.f);
    o0.z = fmaxf(fmaf(dsc, a0.z, b0.z), 0.f);
    o0.w = fmaxf(fmaf(dsc, a0.w, b0.w), 0.f);
    o1.x = fmaxf(fmaf(dsc, a1.x, b1.x), 0.f);
    o1.y = fmaxf(fmaf(dsc, a1.y, b1.y), 0.f);
    o1.z = fmaxf(fmaf(dsc, a1.z, b1.z), 0.f);
    o1.w = fmaxf(fmaf(dsc, a1.w, b1.w), 0.f);
    Out[base + lane] = o0;
    Out[base + 32 + lane] = o1;
}

// ---------------- log_softmax over 64 cols, warp per row, in-place ----------------
__global__ __launch_bounds__(256)
void k_lsm(float* __restrict__ out)
{
    int row = blockIdx.x * 8 + (threadIdx.x >> 5);
    int lane = threadIdx.x & 31;
    size_t b = (size_t)row * 64;
    float v0 = out[b + lane];
    float v1 = out[b + 32 + lane];
    float m = fmaxf(v0, v1);
    #pragma unroll
    for (int d = 16; d; d >>= 1) m = fmaxf(m, __shfl_xor_sync(0xffffffffu, m, d));
    float s = expf(v0 - m) + expf(v1 - m);
    #pragma unroll
    for (int d = 16; d; d >>= 1) s += __shfl_xor_sync(0xffffffffu, s, d);
    float l = m + logf(s);
    out[b + lane] = v0 - l;
    out[b + 32 + lane] = v1 - l;
}

// ---------------- launch ----------------
extern "C" void kernel_launch(void* const* d_in, const int* in_sizes, int n_in,
                              void* d_out, int out_size)
{
    const float* x  = (const float*)d_in[0];
    const int*   ei = (const int*)d_in[1];
    const float* W1 = (const float*)d_in[2];
    const float* b1 = (const float*)d_in[3];
    const float* W2 = (const float*)d_in[4];
    const float* b2 = (const float*)d_in[5];
    const float* Wo = (const float*)d_in[6];
    const float* bo = (const float*)d_in[7];
    float* out = (float*)d_out;

    const int* src = ei;
    const int* dst = ei + NE;

    cudaFuncSetAttribute(gemm_mma<0, 128>, cudaFuncAttributeMaxDynamicSharedMemorySize, 81920);
    cudaFuncSetAttribute(gemm_mma<1, 128>, cudaFuncAttributeMaxDynamicSharedMemorySize, 81920);
    cudaFuncSetAttribute(gemm_mma<2, 64>,  cudaFuncAttributeMaxDynamicSharedMemorySize, 61440);

    // graph prep + weight split (no serial scan: warp-aggregated atomic offsets)
    k_zero<<<(NN + 255) / 256, 256>>>();
    k_deg<<<NE / 256, 256>>>(dst);
    k_convW<<<256, 256>>>(W1, W2, Wo);
    k_off<<<(NN + 255) / 256, 256>>>();
    k_fill<<<NE / 256, 256>>>(src, dst);

    const int GM = (NN + 127) / 128;   // 782

    // layer 1
    gemm_mma<0, 128><<<dim3(GM, 2), 256, 81920>>>(x, nullptr, nullptr);  // bufA = dis*(x@W1)
    k_agg<<<NN / 8, 256>>>(b1);                                          // bufB = relu(...)
    // layer 2
    gemm_mma<1, 128><<<dim3(GM, 2), 256, 81920>>>(nullptr, nullptr, nullptr);
    k_agg<<<NN / 8, 256>>>(b2);
    // output projection + log_softmax
    gemm_mma<2, 64><<<dim3(GM, 1), 256, 61440>>>(nullptr, bo, out);
    k_lsm<<<NN / 8, 256>>>(out);
}